// round 17
// baseline (speedup 1.0000x reference)
#include <cuda_runtime.h>
#include <cuda_bf16.h>

typedef unsigned long long ull;
typedef unsigned int u32;

#define SEQ   1024
#define NBH   64
#define LOG2E 1.4426950408889634f

// per-head max ||k||^2 as float bits (atomicMax; zero-init; idempotent across replays)
__device__ int g_knormi[NBH];
// pre-converted bf16 hi/lo K and V: [bh][n][c] linear, 128B rows
__device__ __align__(16) __nv_bfloat16 g_KH[(size_t)NBH * SEQ * 64];
__device__ __align__(16) __nv_bfloat16 g_KL[(size_t)NBH * SEQ * 64];
__device__ __align__(16) __nv_bfloat16 g_VH[(size_t)NBH * SEQ * 64];
__device__ __align__(16) __nv_bfloat16 g_VL[(size_t)NBH * SEQ * 64];
// pre-converted bf16 hi/lo rel tables, scaled by 8 (cancels Q's 0.125)
__device__ __align__(16) __nv_bfloat16 g_RphH[63 * 64];
__device__ __align__(16) __nv_bfloat16 g_RphL[63 * 64];
__device__ __align__(16) __nv_bfloat16 g_RpwH[64 * 64];   // row 63 zeroed
__device__ __align__(16) __nv_bfloat16 g_RpwL[64 * 64];

// ---------------- helpers ----------------
__device__ __forceinline__ float ex2f(float x) {
    float r; asm("ex2.approx.f32 %0, %1;" : "=f"(r) : "f"(x)); return r;
}
__device__ __forceinline__ u32 smem_to_u32(const void* p) {
    u32 a;
    asm("{ .reg .u64 t; cvta.to.shared.u64 t, %1; cvt.u32.u64 %0, t; }" : "=r"(a) : "l"(p));
    return a;
}
#define SWZ(off) ((off) ^ (((off) >> 3) & 0x70))

__device__ __forceinline__ void ldsm_x4(u32& r0, u32& r1, u32& r2, u32& r3, u32 a) {
    asm volatile("ldmatrix.sync.aligned.m8n8.x4.shared.b16 {%0,%1,%2,%3}, [%4];"
                 : "=r"(r0), "=r"(r1), "=r"(r2), "=r"(r3) : "r"(a));
}
__device__ __forceinline__ void ldsm_x4_t(u32& r0, u32& r1, u32& r2, u32& r3, u32 a) {
    asm volatile("ldmatrix.sync.aligned.m8n8.x4.trans.shared.b16 {%0,%1,%2,%3}, [%4];"
                 : "=r"(r0), "=r"(r1), "=r"(r2), "=r"(r3) : "r"(a));
}
__device__ __forceinline__ void mma_bf16(float* c, const u32* a, u32 b0, u32 b1) {
    asm volatile("mma.sync.aligned.m16n8k16.row.col.f32.bf16.bf16.f32 "
                 "{%0,%1,%2,%3}, {%4,%5,%6,%7}, {%8,%9}, {%0,%1,%2,%3};"
                 : "+f"(c[0]), "+f"(c[1]), "+f"(c[2]), "+f"(c[3])
                 : "r"(a[0]), "r"(a[1]), "r"(a[2]), "r"(a[3]), "r"(b0), "r"(b1));
}
__device__ __forceinline__ void split2(float a, float b, u32& hi, u32& lo) {
    __nv_bfloat162 h = __floats2bfloat162_rn(a, b);
    hi = *(u32*)&h;
    float ra = a - __low2float(h);
    float rb = b - __high2float(h);
    __nv_bfloat162 l = __floats2bfloat162_rn(ra, rb);
    lo = *(u32*)&l;
}
__device__ __forceinline__ void cp16(u32 dst, const void* src) {
    asm volatile("cp.async.cg.shared.global [%0], [%1], 16;" :: "r"(dst), "l"(src) : "memory");
}
#define CP_COMMIT() asm volatile("cp.async.commit_group;" ::: "memory")
#define CP_WAIT(n)  asm volatile("cp.async.wait_group %0;" :: "n"(n) : "memory")

// ---------- kernel C: K/V pre-convert to bf16 hi/lo + per-head knorm ----------
// grid (16, 64), 128 threads: half row per thread (R15 shape — 20.8us).
__global__ void __launch_bounds__(128) kv_convert(const float* __restrict__ k,
                                                  const float* __restrict__ v)
{
    const int tid = threadIdx.x;
    const int bh = blockIdx.y;
    const int b = bh >> 4, hd = bh & 15;
    const int r = blockIdx.x * 64 + (tid >> 1);
    const int cb = (tid & 1) * 32;
    const size_t hoff = (size_t)b * SEQ * 1024 + (size_t)hd * 64;

    const float4* ks = (const float4*)(k + hoff + (size_t)r * 1024 + cb);
    const float4* vs = (const float4*)(v + hoff + (size_t)r * 1024 + cb);
    const size_t eb = (((size_t)bh * SEQ + r) * 64 + cb) >> 1;   // u32 index
    u32* dKH = (u32*)g_KH + eb;
    u32* dKL = (u32*)g_KL + eb;
    u32* dVH = (u32*)g_VH + eb;
    u32* dVL = (u32*)g_VL + eb;

    float ksum = 0.f;
    #pragma unroll
    for (int f = 0; f < 8; f++) {
        float4 x = ks[f];
        ksum += x.x * x.x + x.y * x.y + x.z * x.z + x.w * x.w;
        u32 h0, l0, h1, l1;
        split2(x.x, x.y, h0, l0);
        split2(x.z, x.w, h1, l1);
        dKH[2 * f] = h0; dKH[2 * f + 1] = h1;
        dKL[2 * f] = l0; dKL[2 * f + 1] = l1;
        float4 y = vs[f];
        split2(y.x, y.y, h0, l0);
        split2(y.z, y.w, h1, l1);
        dVH[2 * f] = h0; dVH[2 * f + 1] = h1;
        dVL[2 * f] = l0; dVL[2 * f + 1] = l1;
    }
    // combine column halves, then warp max over rows
    ksum += __shfl_xor_sync(0xffffffffu, ksum, 1);
    #pragma unroll
    for (int m = 2; m <= 16; m <<= 1)
        ksum = fmaxf(ksum, __shfl_xor_sync(0xffffffffu, ksum, m));
    if ((tid & 31) == 0) atomicMax(&g_knormi[bh], __float_as_int(ksum));
}

// ---------- kernel R: rel table convert (x8 scale, bf16 hi/lo) ----------
__global__ void __launch_bounds__(128) rel_convert(const float* __restrict__ rph,
                                                   const float* __restrict__ rpw)
{
    const int tid = threadIdx.x;
    for (int i = tid; i < 63 * 32; i += 128) {   // i indexes float2
        float2 x = ((const float2*)rph)[i];
        u32 h, l;
        split2(x.x * 8.f, x.y * 8.f, h, l);
        ((u32*)g_RphH)[i] = h; ((u32*)g_RphL)[i] = l;
        float2 y = ((const float2*)rpw)[i];
        split2(y.x * 8.f, y.y * 8.f, h, l);
        ((u32*)g_RpwH)[i] = h; ((u32*)g_RpwL)[i] = l;
    }
    if (tid < 32) {   // zero pad row 63 of Rpw
        ((u32*)g_RpwH)[63 * 32 + tid] = 0;
        ((u32*)g_RpwL)[63 * 32 + tid] = 0;
    }
}

// ---------- kernel B: mma.sync bf16 flash attention -------------------------
// 128 threads / 4 warps, BM=64, BN=64, bf16 3-term splits, fixed-bound softmax.
// Prologue overlays Q tiles into buf0 and R tiles into buf1; sG reuses buf0.
// smem = 2x32KB buffers + rHs + sQn = 74.5KB -> 3 CTAs/SM.
#define KV_BUF  32768
#define SM_QH   0                 // prologue only (buf0)
#define SM_QL   8192              // prologue only (buf0)
#define SM_RH   65536             // rHs: 64 x 34 f32 = 8704 (persistent)
#define SM_QN   (SM_RH + 8704)    // 64 f32 row |q| (persistent)
#define SM_TOT  (SM_QN + 256)

__global__ void __launch_bounds__(128, 3)
flash_mma(const float* __restrict__ q, float* __restrict__ out)
{
    extern __shared__ __align__(1024) char smem[];
    float* rHs = (float*)(smem + SM_RH);
    float* sQn = (float*)(smem + SM_QN);
    float* sG  = (float*)smem;                 // relW results in buf0 (prologue only)
    const u32 sbase = smem_to_u32(smem);

    const int tid = threadIdx.x;
    const int lane = tid & 31, wid = tid >> 5;
    const int wm = wid * 16;
    const int l4 = lane >> 2;
    const int l2 = lane & 3;
    const int m0 = blockIdx.x << 6;
    const int bh = blockIdx.y;
    const int b = bh >> 4, hd = bh & 15;
    const int ha = m0 >> 5;

    const size_t hoff = (size_t)b * SEQ * 1024 + (size_t)hd * 64;
    const float* qg = q + hoff;
    float*       og = out + hoff;

    const char* gKH = (const char*)(g_KH + (size_t)bh * SEQ * 64);
    const char* gKL = (const char*)(g_KL + (size_t)bh * SEQ * 64);
    const char* gVH = (const char*)(g_VH + (size_t)bh * SEQ * 64);
    const char* gVL = (const char*)(g_VL + (size_t)bh * SEQ * 64);

    auto issue_kv = [&](int t, int bufi) {
        const u32 db = sbase + (u32)bufi * KV_BUF;
        const u32 go = (u32)t * 8192;
        #pragma unroll
        for (int j = 0; j < 4; j++) {
            const u32 ch = (u32)((tid + 128 * j) * 16);
            const u32 ds = SWZ(ch);
            cp16(db + ds,          gKH + go + ch);
            cp16(db + 8192 + ds,   gKL + go + ch);
            cp16(db + 16384 + ds,  gVH + go + ch);
            cp16(db + 24576 + ds,  gVL + go + ch);
        }
    };

    // ---- stage R tiles into buf1: [RhaH|RhaL|RhbH|RhbL|RwH|RwL] = 32KB ----
    {
        const u32 b1 = sbase + KV_BUF;
        {   // Rh: 32 rows x 4 regions; reg: 0=aH 1=aL 2=bH 3=bL
            const int n = tid & 31, reg = tid >> 5;
            const int hsel = reg >> 1, lo = reg & 1;
            const char* src = (const char*)(lo ? g_RphL : g_RphH)
                              + (size_t)(ha + hsel + 31 - n) * 128;
            const u32 dreg = b1 + (u32)reg * 4096;
            #pragma unroll
            for (int j = 0; j < 8; j++)
                cp16(dreg + SWZ((u32)(n * 128 + 16 * j)), src + 16 * j);
        }
        {   // Rw: 64 rows x 2 regions (H at +16384, L at +24576)
            const int n = tid & 63, lo = tid >> 6;
            const char* src = (const char*)(lo ? g_RpwL : g_RpwH) + (size_t)n * 128;
            const u32 dreg = b1 + 16384u + (u32)lo * 8192;
            #pragma unroll
            for (int j = 0; j < 8; j++)
                cp16(dreg + SWZ((u32)(n * 128 + 16 * j)), src + 16 * j);
        }
        CP_COMMIT();
    }

    // ---- Q convert (scaled, split) into buf0 + row |q| ----
    {
        const int row = tid >> 1, cb = (tid & 1) * 32;
        const float qs = 0.125f * LOG2E;
        const float4* src = (const float4*)(qg + (size_t)(m0 + row) * 1024 + cb);
        float qn = 0.f;
        #pragma unroll
        for (int f = 0; f < 8; f++) {
            float4 x = src[f];
            qn += x.x * x.x + x.y * x.y + x.z * x.z + x.w * x.w;
            u32 h0, l0v, h1, l1v;
            split2(x.x * qs, x.y * qs, h0, l0v);
            split2(x.z * qs, x.w * qs, h1, l1v);
            const u32 bo = (u32)(row * 128 + 2 * (cb + 4 * f));
            const u32 o0 = SWZ(bo), o1 = SWZ(bo + 4);
            *(u32*)(smem + SM_QH + o0) = h0; *(u32*)(smem + SM_QH + o1) = h1;
            *(u32*)(smem + SM_QL + o0) = l0v; *(u32*)(smem + SM_QL + o1) = l1v;
        }
        qn += __shfl_xor_sync(0xffffffffu, qn, 1);
        if (!(tid & 1)) sQn[row] = sqrtf(qn);
    }
    CP_WAIT(0);
    __syncthreads();

    // ---- Q A-fragments (registers, persistent) ----
    u32 aQh[4][4], aQl[4][4];
    {
        const int arow = wm + (lane & 15);
        #pragma unroll
        for (int ks = 0; ks < 4; ks++) {
            const u32 bo = (u32)(arow * 128 + 32 * ks + 16 * (lane >> 4));
            ldsm_x4(aQh[ks][0], aQh[ks][1], aQh[ks][2], aQh[ks][3], sbase + SM_QH + SWZ(bo));
            ldsm_x4(aQl[ks][0], aQl[ks][1], aQl[ks][2], aQl[ks][3], sbase + SM_QL + SWZ(bo));
        }
    }

    // ---- rel GEMMs: relH (own h-group, N=32) and relW (N=64) ----
    float ch[4][4], cw[8][4];
    #pragma unroll
    for (int i = 0; i < 4; i++)
        #pragma unroll
        for (int j = 0; j < 4; j++) ch[i][j] = 0.f;
    #pragma unroll
    for (int i = 0; i < 8; i++)
        #pragma unroll
        for (int j = 0; j < 4; j++) cw[i][j] = 0.f;

    {
        const u32 rhH = sbase + KV_BUF + ((u32)(wid >> 1)) * 8192;
        const u32 rhL = rhH + 4096;
        const u32 rwH = sbase + KV_BUF + 16384;
        const u32 rwL = rwH + 8192;
        #pragma unroll
        for (int ks = 0; ks < 4; ks++) {
            const u32 colb = (u32)(32 * ks + 16 * ((lane >> 3) & 1));
            u32 hh[4][2], hl[4][2];
            #pragma unroll
            for (int u = 0; u < 2; u++) {
                const u32 bo = (u32)((16 * u + ((lane >> 4) & 1) * 8 + (lane & 7)) * 128) + colb;
                ldsm_x4(hh[2 * u][0], hh[2 * u][1], hh[2 * u + 1][0], hh[2 * u + 1][1], rhH + SWZ(bo));
                ldsm_x4(hl[2 * u][0], hl[2 * u][1], hl[2 * u + 1][0], hl[2 * u + 1][1], rhL + SWZ(bo));
            }
            #pragma unroll
            for (int oc = 0; oc < 4; oc++) {
                mma_bf16(ch[oc], aQh[ks], hh[oc][0], hh[oc][1]);
                mma_bf16(ch[oc], aQh[ks], hl[oc][0], hl[oc][1]);
                mma_bf16(ch[oc], aQl[ks], hh[oc][0], hh[oc][1]);
            }
            u32 wh[8][2], wl[8][2];
            #pragma unroll
            for (int u = 0; u < 4; u++) {
                const u32 bo = (u32)((16 * u + ((lane >> 4) & 1) * 8 + (lane & 7)) * 128) + colb;
                ldsm_x4(wh[2 * u][0], wh[2 * u][1], wh[2 * u + 1][0], wh[2 * u + 1][1], rwH + SWZ(bo));
                ldsm_x4(wl[2 * u][0], wl[2 * u][1], wl[2 * u + 1][0], wl[2 * u + 1][1], rwL + SWZ(bo));
            }
            #pragma unroll
            for (int oc = 0; oc < 8; oc++) {
                mma_bf16(cw[oc], aQh[ks], wh[oc][0], wh[oc][1]);
                mma_bf16(cw[oc], aQh[ks], wl[oc][0], wl[oc][1]);
                mma_bf16(cw[oc], aQl[ks], wh[oc][0], wh[oc][1]);
            }
        }
    }
    __syncthreads();   // all ldsm of buf0 (Q) and buf1 (R) done; buf0 -> sG

    // ---- store relH -> rHs (stride 34), relW -> sG (buf0, stride 66) ----
    {
        const int r0 = wm + l4, r1 = r0 + 8;
        #pragma unroll
        for (int oc = 0; oc < 4; oc++) {
            const int c = 8 * oc + 2 * l2;
            rHs[r0 * 34 + c] = ch[oc][0]; rHs[r0 * 34 + c + 1] = ch[oc][1];
            rHs[r1 * 34 + c] = ch[oc][2]; rHs[r1 * 34 + c + 1] = ch[oc][3];
        }
        #pragma unroll
        for (int oc = 0; oc < 8; oc++) {
            const int c = 8 * oc + 2 * l2;
            sG[r0 * 66 + c] = cw[oc][0]; sG[r0 * 66 + c + 1] = cw[oc][1];
            sG[r1 * 66 + c] = cw[oc][2]; sG[r1 * 66 + c + 1] = cw[oc][3];
        }
    }
    __syncthreads();

    // ---- per-thread rel_w regs + fixed row bounds ----
    const int r0loc = wm + l4, r1loc = r0loc + 8;
    const int r0g = m0 + r0loc, r1g = m0 + r1loc;
    const int w0 = r0loc & 31, w1 = r1loc & 31;
    float rw0[8], rw1[8], rowM0, rowM1, lsum0 = 0.f, lsum1 = 0.f;
    {
        const float* G0 = sG + r0loc * 66;
        const float* G1 = sG + r1loc * 66;
        #pragma unroll
        for (int j = 0; j < 4; j++) {
            const int kw = 8 * j + 2 * l2;
            rw0[2 * j]     = G0[w0 + 31 - kw];
            rw0[2 * j + 1] = G0[w0 + 30 - kw];
            rw1[2 * j]     = G1[w1 + 31 - kw];
            rw1[2 * j + 1] = G1[w1 + 30 - kw];
        }
        const float kn = sqrtf(__int_as_float(g_knormi[bh])) * (0.125f * LOG2E);
        float mh0 = -3.0e38f, mh1 = -3.0e38f, mw0 = -3.0e38f, mw1 = -3.0e38f;
        #pragma unroll 8
        for (int j = 0; j < 32; j++) {
            mh0 = fmaxf(mh0, rHs[r0loc * 34 + j]);
            mh1 = fmaxf(mh1, rHs[r1loc * 34 + j]);
            mw0 = fmaxf(mw0, G0[w0 + j]);
            mw1 = fmaxf(mw1, G1[w1 + j]);
        }
        rowM0 = mh0 + mw0 + sQn[r0loc] * kn;
        rowM1 = mh1 + mw1 + sQn[r1loc] * kn;
    }
    __syncthreads();   // everyone done reading sG (buf0) before tile-0 issue

    issue_kv(0, 0);
    CP_COMMIT();

    float o[8][4];
    #pragma unroll
    for (int i = 0; i < 8; i++)
        #pragma unroll
        for (int j = 0; j < 4; j++) o[i][j] = 0.f;

    for (int t = 0; t < 16; t++) {
        if (t < 15) { issue_kv(t + 1, (t + 1) & 1); CP_COMMIT(); }
        if (t < 15) { CP_WAIT(1); } else { CP_WAIT(0); }
        __syncthreads();

        const u32 kb = sbase + (u32)(t & 1) * KV_BUF;

        // ---- S = Qh*Kh + Qh*Kl + Ql*Kh ----
        float s[8][4];
        #pragma unroll
        for (int i = 0; i < 8; i++)
            #pragma unroll
            for (int j = 0; j < 4; j++) s[i][j] = 0.f;

        #pragma unroll
        for (int ks = 0; ks < 4; ks++) {
            u32 bKh[8][2], bKl[8][2];
            const u32 colb = (u32)(32 * ks + 16 * ((lane >> 3) & 1));
            #pragma unroll
            for (int u = 0; u < 4; u++) {
                const u32 bo = (u32)((16 * u + ((lane >> 4) & 1) * 8 + (lane & 7)) * 128) + colb;
                ldsm_x4(bKh[2 * u][0], bKh[2 * u][1], bKh[2 * u + 1][0], bKh[2 * u + 1][1],
                        kb + SWZ(bo));
                ldsm_x4(bKl[2 * u][0], bKl[2 * u][1], bKl[2 * u + 1][0], bKl[2 * u + 1][1],
                        kb + 8192 + SWZ(bo));
            }
            #pragma unroll
            for (int oc = 0; oc < 8; oc++) {
                mma_bf16(s[oc], aQh[ks], bKh[oc][0], bKh[oc][1]);
                mma_bf16(s[oc], aQh[ks], bKl[oc][0], bKl[oc][1]);
                mma_bf16(s[oc], aQl[ks], bKh[oc][0], bKh[oc][1]);
            }
        }

        // ---- softmax (fixed bound) + build P fragments in registers ----
        const int kh0 = 2 * t;
        const float rhA0 = rHs[r0loc * 34 + kh0]     - rowM0;
        const float rhB0 = rHs[r0loc * 34 + kh0 + 1] - rowM0;
        const float rhA1 = rHs[r1loc * 34 + kh0]     - rowM1;
        const float rhB1 = rHs[r1loc * 34 + kh0 + 1] - rowM1;

        u32 aPh[4][4], aPl[4][4];
        #pragma unroll
        for (int oc = 0; oc < 8; oc++) {
            const int j = oc & 3;
            const float c0 = (oc < 4) ? rhA0 : rhB0;
            const float c1 = (oc < 4) ? rhA1 : rhB1;
            float p0 = ex2f(s[oc][0] + rw0[2 * j]     + c0);
            float p1 = ex2f(s[oc][1] + rw0[2 * j + 1] + c0);
            float p2 = ex2f(s[oc][2] + rw1[2 * j]     + c1);
            float p3 = ex2f(s[oc][3] + rw1[2 * j + 1] + c1);
            lsum0 += p0 + p1;
            lsum1 += p2 + p3;
            u32 h01, l01, h23, l23;
            split2(p0, p1, h01, l01);
            split2(p2, p3, h23, l23);
            const int kf = oc >> 1, hi = (oc & 1) * 2;
            aPh[kf][hi] = h01; aPh[kf][hi + 1] = h23;
            aPl[kf][hi] = l01; aPl[kf][hi + 1] = l23;
        }

        // ---- O += Ph*Vh + Ph*Vl + Pl*Vh ----
        #pragma unroll
        for (int kf = 0; kf < 4; kf++) {
            u32 bVh[8][2], bVl[8][2];
            const int nb = 16 * kf;
            #pragma unroll
            for (int u = 0; u < 4; u++) {
                const u32 bo = (u32)((nb + ((lane >> 3) & 1) * 8 + (lane & 7)) * 128
                                     + 32 * u + 16 * ((lane >> 4) & 1));
                ldsm_x4_t(bVh[2 * u][0], bVh[2 * u][1], bVh[2 * u + 1][0], bVh[2 * u + 1][1],
                          kb + 16384 + SWZ(bo));
                ldsm_x4_t(bVl[2 * u][0], bVl[2 * u][1], bVl[2 * u + 1][0], bVl[2 * u + 1][1],
                          kb + 24576 + SWZ(bo));
            }
            #pragma unroll
            for (int du = 0; du < 8; du++) {
                mma_bf16(o[du], aPh[kf], bVh[du][0], bVh[du][1]);
                mma_bf16(o[du], aPh[kf], bVl[du][0], bVl[du][1]);
                mma_bf16(o[du], aPl[kf], bVh[du][0], bVh[du][1]);
            }
        }
        __syncthreads();   // release read buffer before next issue overwrites it
    }

    // ---- finalize ----
    lsum0 += __shfl_xor_sync(0xffffffffu, lsum0, 1);
    lsum0 += __shfl_xor_sync(0xffffffffu, lsum0, 2);
    lsum1 += __shfl_xor_sync(0xffffffffu, lsum1, 1);
    lsum1 += __shfl_xor_sync(0xffffffffu, lsum1, 2);
    const float inv0 = __fdividef(1.0f, lsum0);
    const float inv1 = __fdividef(1.0f, lsum1);

    float* op0 = og + (size_t)r0g * 1024;
    float* op1 = og + (size_t)r1g * 1024;
    #pragma unroll
    for (int du = 0; du < 8; du++) {
        const int d = 8 * du + 2 * l2;
        *(float2*)(op0 + d) = make_float2(o[du][0] * inv0, o[du][1] * inv0);
        *(float2*)(op1 + d) = make_float2(o[du][2] * inv1, o[du][3] * inv1);
    }
}

extern "C" void kernel_launch(void* const* d_in, const int* in_sizes, int n_in,
                              void* d_out, int out_size)
{
    const float* q   = (const float*)d_in[0];
    const float* k   = (const float*)d_in[1];
    const float* v   = (const float*)d_in[2];
    const float* rph = (const float*)d_in[3];
    const float* rpw = (const float*)d_in[4];
    float* out = (float*)d_out;

    dim3 cg(16, 64);
    kv_convert<<<cg, 128>>>(k, v);
    rel_convert<<<1, 128>>>(rph, rpw);

    cudaFuncSetAttribute(flash_mma, cudaFuncAttributeMaxDynamicSharedMemorySize, SM_TOT);
    dim3 grid(SEQ / 64, NBH);
    flash_mma<<<grid, 128, SM_TOT>>>(q, out);
}